// round 1
// baseline (speedup 1.0000x reference)
#include <cuda_runtime.h>

#define Bv 8
#define Sv 100
#define Tv 1200
#define NMELv 80
#define DMv 128
#define KKv 9
#define PADm 4

// Scratch (no cudaMalloc allowed): x after conv stack, and GRU input projections.
__device__ float g_x[Bv * Tv * NMELv];          // 3.07 MB
__device__ float g_xg[Bv * Tv * 768];           // 29.5 MB  [frame][fwd 0:384 | bwd 384:768]

__device__ __forceinline__ float sigmoidf_fast(float x) {
    return __fdividef(1.f, 1.f + __expf(-x));
}
__device__ __forceinline__ float tanhf_fast(float x) {
    // tanh(x) = 1 - 2/(e^{2x}+1); inf-safe, abs err ~1e-7
    return 1.f - __fdividef(2.f, __expf(2.f * x) + 1.f);
}

// ---------------------------------------------------------------------------
// Kernel 1: fused conv1 -> BN/ReLU -> conv2 -> BN/ReLU per (b, t) frame.
// Both convs run along the 80 mel bins (kernel 9, pad 4). One block per frame.
// ---------------------------------------------------------------------------
__global__ __launch_bounds__(256) void conv_kernel(
    const float* __restrict__ mel, const int* __restrict__ mel_len,
    const float* __restrict__ w1, const float* __restrict__ g1, const float* __restrict__ be1,
    const float* __restrict__ w2, const float* __restrict__ g2, const float* __restrict__ be2)
{
    int bt = blockIdx.x;
    int b = bt / Tv, t = bt - b * Tv;
    if (t >= mel_len[b]) return;   // frames past mel_len are never consumed

    extern __shared__ float sm[];
    float* y1p  = sm;                    // 128 x 88 (padded rows)
    float* melp = y1p + DMv * 88;        // 88
    float* w1s  = melp + 88;             // 1152
    float* w2s  = w1s + DMv * KKv;       // 1152
    float* sc1  = w2s + DMv * KKv;       // 128
    float* bb1  = sc1 + DMv;             // 128
    float* part = bb1 + DMv;             // 240
    int tid = threadIdx.x;

    if (tid < 88)
        melp[tid] = (tid >= PADm && tid < NMELv + PADm) ? mel[bt * NMELv + tid - PADm] : 0.f;
    for (int i = tid; i < DMv * KKv; i += 256) { w1s[i] = w1[i]; w2s[i] = w2[i]; }
    if (tid < DMv) { sc1[tid] = g1[tid] * rsqrtf(1.f + 1e-5f); bb1[tid] = be1[tid]; }
    // zero the m-padding columns of y1p
    for (int i = tid; i < DMv * 8; i += 256) {
        int c = i >> 3, p = i & 7;
        y1p[c * 88 + (p < 4 ? p : NMELv + p)] = 0.f;
    }
    __syncthreads();

    // conv1: y1[c][m] = relu(bn1(sum_k w1[c][k] * melp[m+k]))
    for (int idx = tid; idx < DMv * NMELv; idx += 256) {
        int c = idx / NMELv, m = idx - c * NMELv;
        float acc = 0.f;
        #pragma unroll
        for (int k = 0; k < KKv; k++) acc = fmaf(w1s[c * KKv + k], melp[m + k], acc);
        y1p[c * 88 + m + PADm] = fmaxf(fmaf(acc, sc1[c], bb1[c]), 0.f);
    }
    __syncthreads();

    // conv2: split the 128-channel reduction 3 ways per m
    if (tid < 240) {
        int m = tid / 3, p = tid - (tid / 3) * 3;
        int c0 = p * 43, c1 = (p == 2) ? DMv : c0 + 43;
        float acc = 0.f;
        for (int c = c0; c < c1; c++) {
            #pragma unroll
            for (int k = 0; k < KKv; k++) acc = fmaf(w2s[c * KKv + k], y1p[c * 88 + m + k], acc);
        }
        part[m * 3 + p] = acc;
    }
    __syncthreads();

    if (tid < NMELv) {
        float s2 = g2[0] * rsqrtf(1.f + 1e-5f);
        float v = fmaxf(fmaf(part[tid * 3] + part[tid * 3 + 1] + part[tid * 3 + 2], s2, be2[0]), 0.f);
        g_x[bt * NMELv + tid] = v;
    }
}

// ---------------------------------------------------------------------------
// Kernel 2: input projections as a tiled GEMM.
// XG(9600 x 768) = X(9600 x 80) @ [w_ih_f ; w_ih_b]^T + bias.
// Tile: 64 frames x 128 gates, K=80 fully resident in smem (transposed, padded).
// ---------------------------------------------------------------------------
__global__ __launch_bounds__(256) void proj_kernel(
    const float* __restrict__ w_ih_f, const float* __restrict__ b_ih_f,
    const float* __restrict__ w_ih_b, const float* __restrict__ b_ih_b)
{
    int f0 = blockIdx.x * 64;
    int g0 = blockIdx.y * 128;
    extern __shared__ float sm[];
    float* Xs = sm;             // [80][65]  (padded to avoid bank conflicts)
    float* Ws = sm + 80 * 65;   // [80][129]
    int tid = threadIdx.x;

    for (int i = tid; i < 64 * NMELv; i += 256) {
        int r = i / NMELv, m = i - r * NMELv;
        Xs[m * 65 + r] = g_x[(f0 + r) * NMELv + m];
    }
    const float* wsrc = (g0 < 384) ? (w_ih_f + g0 * NMELv) : (w_ih_b + (g0 - 384) * NMELv);
    const float* bsrc = (g0 < 384) ? (b_ih_f + g0) : (b_ih_b + (g0 - 384));
    for (int i = tid; i < 128 * NMELv; i += 256) {
        int c = i / NMELv, m = i - c * NMELv;
        Ws[m * 129 + c] = wsrc[c * NMELv + m];
    }
    __syncthreads();

    int tx = tid & 15, ty = tid >> 4;   // 8 gates x 4 frames per thread
    float acc[8][4];
    #pragma unroll
    for (int u = 0; u < 8; u++)
        #pragma unroll
        for (int v = 0; v < 4; v++) acc[u][v] = 0.f;

    for (int m = 0; m < NMELv; m++) {
        float xv[4], wv[8];
        #pragma unroll
        for (int v = 0; v < 4; v++) xv[v] = Xs[m * 65 + ty * 4 + v];
        #pragma unroll
        for (int u = 0; u < 8; u++) wv[u] = Ws[m * 129 + tx + 16 * u];
        #pragma unroll
        for (int u = 0; u < 8; u++)
            #pragma unroll
            for (int v = 0; v < 4; v++) acc[u][v] = fmaf(wv[u], xv[v], acc[u][v]);
    }
    #pragma unroll
    for (int u = 0; u < 8; u++) {
        int c = tx + 16 * u;
        float bias = bsrc[c];
        #pragma unroll
        for (int v = 0; v < 4; v++) {
            int r = ty * 4 + v;
            g_xg[(f0 + r) * 768 + g0 + c] = acc[u][v] + bias;
        }
    }
}

// ---------------------------------------------------------------------------
// Kernel 3: segment GRU. Resets make each (b, s, dir) chain independent
// (length = duration <= 12). One block per (dir, s), batching all 8 b.
// w_hh lives in REGISTERS: thread g holds row g (128 floats). h in smem
// (broadcast reads). Per step: 393K FMA/block.
// ---------------------------------------------------------------------------
__global__ void __launch_bounds__(384, 1) gru_kernel(
    const int* __restrict__ durations, const int* __restrict__ src_len,
    const float* __restrict__ w_hh_f, const float* __restrict__ b_hh_f,
    const float* __restrict__ w_hh_b, const float* __restrict__ b_hh_b,
    float* __restrict__ out)
{
    int blk = blockIdx.x;
    int dir = blk / Sv;
    int s = blk - dir * Sv;
    int g = threadIdx.x;

    __shared__ __align__(16) float h_s[8][128];
    __shared__ float gate_s[8][256];
    __shared__ float hn_s[8][128];
    __shared__ float xn_s[8][128];
    __shared__ int start_s[8], dur_s[8];
    __shared__ int maxdur_s;

    if (g < 8) {
        int st = 0;
        for (int ss = 0; ss < s; ss++) st += durations[g * Sv + ss];
        start_s[g] = st;
        dur_s[g] = durations[g * Sv + s];
    }
    __syncthreads();
    if (g == 0) {
        int mx = 0;
        for (int bb = 0; bb < 8; bb++) mx = max(mx, dur_s[bb]);
        maxdur_s = mx;
    }
    float* hflat = &h_s[0][0];
    for (int i = g; i < 8 * 128; i += 384) hflat[i] = 0.f;
    __syncthreads();

    const float* whh = dir ? w_hh_b : w_hh_f;
    const float* bhh = dir ? b_hh_b : b_hh_f;
    float w[128];
    {
        const float4* wp = reinterpret_cast<const float4*>(whh + g * 128);
        #pragma unroll
        for (int k4 = 0; k4 < 32; k4++) {
            float4 v = wp[k4];
            w[4 * k4 + 0] = v.x; w[4 * k4 + 1] = v.y;
            w[4 * k4 + 2] = v.z; w[4 * k4 + 3] = v.w;
        }
    }
    float bg = bhh[g];
    int maxd = maxdur_s;
    const float* xgb = g_xg + dir * 384 + g;

    for (int i = 0; i < maxd; i++) {
        float acc[8];
        #pragma unroll
        for (int bb = 0; bb < 8; bb++) acc[bb] = bg;
        #pragma unroll
        for (int k4 = 0; k4 < 32; k4++) {
            #pragma unroll
            for (int bb = 0; bb < 8; bb++) {
                float4 hv = reinterpret_cast<const float4*>(&h_s[bb][0])[k4];
                acc[bb] = fmaf(w[4 * k4 + 0], hv.x, acc[bb]);
                acc[bb] = fmaf(w[4 * k4 + 1], hv.y, acc[bb]);
                acc[bb] = fmaf(w[4 * k4 + 2], hv.z, acc[bb]);
                acc[bb] = fmaf(w[4 * k4 + 3], hv.w, acc[bb]);
            }
        }
        float xv[8];
        #pragma unroll
        for (int bb = 0; bb < 8; bb++) {
            int d = dur_s[bb];
            int ie = min(i, d - 1);                      // clamp: inactive segs read a valid frame
            int t = start_s[bb] + (dir ? (d - 1 - ie) : ie);
            xv[bb] = xgb[(bb * Tv + t) * 768];
        }
        if (g < 256) {
            #pragma unroll
            for (int bb = 0; bb < 8; bb++)
                gate_s[bb][g] = sigmoidf_fast(xv[bb] + acc[bb]);   // r (g<128) and z (128<=g<256)
        } else {
            int j = g - 256;
            #pragma unroll
            for (int bb = 0; bb < 8; bb++) {
                hn_s[bb][j] = acc[bb];
                xn_s[bb][j] = xv[bb];
            }
        }
        __syncthreads();
        if (g < 128) {
            #pragma unroll
            for (int bb = 0; bb < 8; bb++) {
                float r = gate_s[bb][g];
                float z = gate_s[bb][128 + g];
                float n = tanhf_fast(fmaf(r, hn_s[bb][g], xn_s[bb][g]));
                float hnew = fmaf(z, h_s[bb][g] - n, n);   // (1-z)*n + z*h
                if (i < dur_s[bb]) h_s[bb][g] = hnew;      // freeze h after segment end
            }
        }
        __syncthreads();
    }

    if (g < 128) {
        #pragma unroll
        for (int bb = 0; bb < 8; bb++) {
            float v = (s < src_len[bb]) ? h_s[bb][g] : 0.f;
            out[(bb * Sv + s) * 256 + dir * 128 + g] = v;
        }
    }
}

// ---------------------------------------------------------------------------
extern "C" void kernel_launch(void* const* d_in, const int* in_sizes, int n_in,
                              void* d_out, int out_size) {
    const float* mel      = (const float*)d_in[0];
    const int*   durations= (const int*)d_in[1];
    const int*   mel_len  = (const int*)d_in[2];
    const int*   src_len  = (const int*)d_in[3];
    const float* w1       = (const float*)d_in[4];
    const float* g1       = (const float*)d_in[5];
    const float* be1      = (const float*)d_in[6];
    const float* w2       = (const float*)d_in[7];
    const float* g2       = (const float*)d_in[8];
    const float* be2      = (const float*)d_in[9];
    const float* w_ih_f   = (const float*)d_in[10];
    const float* w_hh_f   = (const float*)d_in[11];
    const float* b_ih_f   = (const float*)d_in[12];
    const float* b_hh_f   = (const float*)d_in[13];
    const float* w_ih_b   = (const float*)d_in[14];
    const float* w_hh_b   = (const float*)d_in[15];
    const float* b_ih_b   = (const float*)d_in[16];
    const float* b_hh_b   = (const float*)d_in[17];
    float* out = (float*)d_out;

    size_t conv_smem = (size_t)(DMv * 88 + 88 + DMv * KKv * 2 + DMv * 2 + 240) * sizeof(float);
    size_t proj_smem = (size_t)(80 * 65 + 80 * 129) * sizeof(float);
    cudaFuncSetAttribute(conv_kernel, cudaFuncAttributeMaxDynamicSharedMemorySize, (int)conv_smem);
    cudaFuncSetAttribute(proj_kernel, cudaFuncAttributeMaxDynamicSharedMemorySize, (int)proj_smem);

    conv_kernel<<<Bv * Tv, 256, conv_smem>>>(mel, mel_len, w1, g1, be1, w2, g2, be2);
    proj_kernel<<<dim3(150, 6), 256, proj_smem>>>(w_ih_f, b_ih_f, w_ih_b, b_ih_b);
    gru_kernel<<<2 * Sv, 384>>>(durations, src_len, w_hh_f, b_hh_f, w_hh_b, b_hh_b, out);
}

// round 2
// speedup vs baseline: 2.8223x; 2.8223x over previous
#include <cuda_runtime.h>

#define Bv 8
#define Sv 100
#define Tv 1200
#define NMELv 80
#define DMv 128
#define KKv 9

typedef unsigned long long u64;

// Scratch (no cudaMalloc allowed)
__device__ float g_x[Bv * Tv * NMELv];          // conv output, 3.07 MB
__device__ float g_xg[Bv * Tv * 768];           // GRU input projections, 29.5 MB

__device__ __forceinline__ float sigmoidf_fast(float x) {
    return __fdividef(1.f, 1.f + __expf(-x));
}
__device__ __forceinline__ float tanhf_fast(float x) {
    return 1.f - __fdividef(2.f, __expf(2.f * x) + 1.f);
}

// ---- packed f32x2 helpers (Blackwell sm_103a) ----
__device__ __forceinline__ u64 pk2(float lo, float hi) {
    u64 r; asm("mov.b64 %0, {%1, %2};" : "=l"(r) : "f"(lo), "f"(hi)); return r;
}
__device__ __forceinline__ void up2(u64 v, float& lo, float& hi) {
    asm("mov.b64 {%0, %1}, %2;" : "=f"(lo), "=f"(hi) : "l"(v));
}
__device__ __forceinline__ u64 fma2(u64 a, u64 b, u64 c) {
    u64 d; asm("fma.rn.f32x2 %0, %1, %2, %3;" : "=l"(d) : "l"(a), "l"(b), "l"(c)); return d;
}

// ---------------------------------------------------------------------------
// Kernel 1: fused conv stack, register-resident, f32x2 packed.
// 128 threads = 128 channels. Pair layout: (m, m+40).
// Y[j] (j in [0,88)) = relu(bn1(conv1))[j-4], zero-padded; packed Yp[j]=(Y[j],Y[j+40]).
// ---------------------------------------------------------------------------
__global__ __launch_bounds__(128) void conv_kernel(
    const float* __restrict__ mel, const int* __restrict__ mel_len,
    const float* __restrict__ w1, const float* __restrict__ g1, const float* __restrict__ be1,
    const float* __restrict__ w2, const float* __restrict__ g2, const float* __restrict__ be2)
{
    int bt = blockIdx.x;
    int b = bt / Tv, t = bt - b * Tv;
    if (t >= mel_len[b]) return;

    extern __shared__ float sm[];
    float* ps  = sm;                       // [80][132] reduce buffer
    u64*   mp2 = (u64*)(sm + 80 * 132);    // 48 packed mel pairs
    int c = threadIdx.x;

    // Build packed, padded mel: M[j] = mel[j-4] for j in [4,84), else 0.
    // mp2[j] = (M[j], M[j+40]), j = 0..47
    if (c < 48) {
        float lo = (c >= 4) ? mel[bt * NMELv + c - 4] : 0.f;
        float hi = (c < 44) ? mel[bt * NMELv + c + 36] : 0.f;
        mp2[c] = pk2(lo, hi);
    }

    // Weights (BN scales folded in)
    float sc1c = g1[c] * rsqrtf(1.f + 1e-5f);
    float bb1c = be1[c];
    float s2   = g2[0] * rsqrtf(1.f + 1e-5f);
    u64 w1p[KKv], w2p[KKv];
    #pragma unroll
    for (int k = 0; k < KKv; k++) {
        float a = w1[c * KKv + k] * sc1c;  w1p[k] = pk2(a, a);
        float d = w2[c * KKv + k] * s2;    w2p[k] = pk2(d, d);
    }
    u64 bbp = pk2(bb1c, bb1c);
    __syncthreads();

    // conv1 with sliding register window over mel pairs
    u64 Yp[48];
    u64 ring[9];
    #pragma unroll
    for (int j = 0; j < 8; j++) ring[j] = mp2[j];
    #pragma unroll
    for (int m = 0; m < 40; m++) {
        ring[(m + 8) % 9] = mp2[m + 8];
        u64 acc = bbp;
        #pragma unroll
        for (int k = 0; k < KKv; k++) acc = fma2(w1p[k], ring[(m + k) % 9], acc);
        float a, h; up2(acc, a, h);
        Yp[m + 4] = pk2(fmaxf(a, 0.f), fmaxf(h, 0.f));
    }
    // Edge pairs: Yp[j]=(0, lo(Yp[40+j])), Yp[44+j]=(hi(Yp[4+j]), 0)
    #pragma unroll
    for (int j = 0; j < 4; j++) {
        float a, h;
        up2(Yp[40 + j], a, h); Yp[j]      = pk2(0.f, a);
        up2(Yp[4 + j],  a, h); Yp[44 + j] = pk2(h, 0.f);
    }

    // conv2 (per-channel contribution), write partials to smem
    #pragma unroll
    for (int m = 0; m < 40; m++) {
        u64 acc = 0ull;
        #pragma unroll
        for (int k = 0; k < KKv; k++) acc = fma2(w2p[k], Yp[m + k], acc);
        float a, h; up2(acc, a, h);
        ps[m * 132 + c]        = a;
        ps[(m + 40) * 132 + c] = h;
    }
    __syncthreads();

    // Cross-channel reduction: thread m sums 128 partials
    if (c < NMELv) {
        const float4* row = (const float4*)(ps + c * 132);
        float sum = 0.f;
        #pragma unroll
        for (int q = 0; q < 32; q++) {
            float4 v = row[q];
            sum += (v.x + v.y) + (v.z + v.w);
        }
        g_x[bt * NMELv + c] = fmaxf(sum + be2[0], 0.f);
    }
}

// ---------------------------------------------------------------------------
// Kernel 2: input projection GEMM, f32x2 packed over frame pairs.
// XG(9600 x 768) = X(9600 x 80) @ [w_ih_f ; w_ih_b]^T + bias.
// ---------------------------------------------------------------------------
__global__ __launch_bounds__(256) void proj_kernel(
    const float* __restrict__ w_ih_f, const float* __restrict__ b_ih_f,
    const float* __restrict__ w_ih_b, const float* __restrict__ b_ih_b)
{
    int f0 = blockIdx.x * 64;
    int g0 = blockIdx.y * 128;
    extern __shared__ float sm[];
    float* Xs = sm;             // [80][66] (even pad -> 8B-aligned pairs)
    float* Ws = sm + 80 * 66;   // [80][129]
    int tid = threadIdx.x;

    for (int i = tid; i < 64 * NMELv; i += 256) {
        int r = i / NMELv, m = i - r * NMELv;
        Xs[m * 66 + r] = g_x[(f0 + r) * NMELv + m];
    }
    const float* wsrc = (g0 < 384) ? (w_ih_f + g0 * NMELv) : (w_ih_b + (g0 - 384) * NMELv);
    const float* bsrc = (g0 < 384) ? (b_ih_f + g0) : (b_ih_b + (g0 - 384));
    for (int i = tid; i < 128 * NMELv; i += 256) {
        int cc = i / NMELv, m = i - cc * NMELv;
        Ws[m * 129 + cc] = wsrc[cc * NMELv + m];
    }
    __syncthreads();

    int tx = tid & 15, ty = tid >> 4;   // 8 gates x (2 frame-pairs) per thread
    u64 acc[8][2];
    #pragma unroll
    for (int u = 0; u < 8; u++) { acc[u][0] = 0ull; acc[u][1] = 0ull; }

    #pragma unroll 4
    for (int m = 0; m < NMELv; m++) {
        u64 x0 = *(const u64*)&Xs[m * 66 + ty * 4];
        u64 x1 = *(const u64*)&Xs[m * 66 + ty * 4 + 2];
        #pragma unroll
        for (int u = 0; u < 8; u++) {
            float wv = Ws[m * 129 + tx + 16 * u];
            u64 wp = pk2(wv, wv);
            acc[u][0] = fma2(wp, x0, acc[u][0]);
            acc[u][1] = fma2(wp, x1, acc[u][1]);
        }
    }
    #pragma unroll
    for (int u = 0; u < 8; u++) {
        int cc = tx + 16 * u;
        float bias = bsrc[cc];
        float a0, a1, a2, a3;
        up2(acc[u][0], a0, a1);
        up2(acc[u][1], a2, a3);
        int base = (f0 + ty * 4) * 768 + g0 + cc;
        g_xg[base]            = a0 + bias;
        g_xg[base + 768]      = a1 + bias;
        g_xg[base + 2 * 768]  = a2 + bias;
        g_xg[base + 3 * 768]  = a3 + bias;
    }
}

// ---------------------------------------------------------------------------
// Kernel 3: segment GRU, 4 batches/block (grid 400), f32x2 batch pairs.
// h layout [k][bb] so (bb0,bb1)/(bb2,bb3) pairs are contiguous 8B words.
// ---------------------------------------------------------------------------
#define NBg 4
__global__ void __launch_bounds__(384, 1) gru_kernel(
    const int* __restrict__ durations, const int* __restrict__ src_len,
    const float* __restrict__ w_hh_f, const float* __restrict__ b_hh_f,
    const float* __restrict__ w_hh_b, const float* __restrict__ b_hh_b,
    float* __restrict__ out)
{
    int blk = blockIdx.x;               // 0..399
    int dir = blk / 200;
    int r = blk - dir * 200;
    int s = r >> 1, bgrp = r & 1, b0 = bgrp * 4;
    int g = threadIdx.x;

    __shared__ __align__(16) float h4[128][4];
    __shared__ float gate_s[NBg][256];
    __shared__ float hn_s[NBg][128];
    __shared__ float xn_s[NBg][128];
    __shared__ int start_s[NBg], dur_s[NBg];
    __shared__ int maxdur_s;

    if (g < NBg) {
        int b = b0 + g;
        int st = 0;
        for (int ss = 0; ss < s; ss++) st += durations[b * Sv + ss];
        start_s[g] = st;
        dur_s[g] = durations[b * Sv + s];
    }
    for (int i = g; i < 128 * 4; i += 384) ((float*)h4)[i] = 0.f;
    __syncthreads();
    if (g == 0) {
        int mx = 0;
        for (int bb = 0; bb < NBg; bb++) mx = max(mx, dur_s[bb]);
        maxdur_s = mx;
    }
    __syncthreads();

    const float* whh = dir ? w_hh_b : w_hh_f;
    float w[128];
    {
        const float4* wp = reinterpret_cast<const float4*>(whh + g * 128);
        #pragma unroll
        for (int k4 = 0; k4 < 32; k4++) {
            float4 v = wp[k4];
            w[4 * k4 + 0] = v.x; w[4 * k4 + 1] = v.y;
            w[4 * k4 + 2] = v.z; w[4 * k4 + 3] = v.w;
        }
    }
    float bias_g = (dir ? b_hh_b : b_hh_f)[g];
    int maxd = maxdur_s;
    int st[NBg], du[NBg];
    #pragma unroll
    for (int bb = 0; bb < NBg; bb++) { st[bb] = start_s[bb]; du[bb] = dur_s[bb]; }
    const float* xgb = g_xg + dir * 384 + g;

    for (int i = 0; i < maxd; i++) {
        // prefetch x projections (independent LDGs, hide under matmul)
        float xv[NBg];
        #pragma unroll
        for (int bb = 0; bb < NBg; bb++) {
            int d = du[bb];
            int ie = min(i, d - 1);
            int t = st[bb] + (dir ? (d - 1 - ie) : ie);
            xv[bb] = xgb[((b0 + bb) * Tv + t) * 768];
        }
        u64 acc0 = pk2(bias_g, bias_g), acc1 = acc0;
        const u64* hrow = (const u64*)h4;
        #pragma unroll
        for (int k = 0; k < 128; k++) {
            u64 wk = pk2(w[k], w[k]);
            acc0 = fma2(wk, hrow[2 * k],     acc0);
            acc1 = fma2(wk, hrow[2 * k + 1], acc1);
        }
        float acc[NBg];
        up2(acc0, acc[0], acc[1]);
        up2(acc1, acc[2], acc[3]);

        if (g < 256) {
            #pragma unroll
            for (int bb = 0; bb < NBg; bb++)
                gate_s[bb][g] = sigmoidf_fast(xv[bb] + acc[bb]);   // r, z
        } else {
            int j = g - 256;
            #pragma unroll
            for (int bb = 0; bb < NBg; bb++) {
                hn_s[bb][j] = acc[bb];
                xn_s[bb][j] = xv[bb];
            }
        }
        __syncthreads();
        if (g < 128) {
            float4 hold = *(float4*)&h4[g][0];
            float ho[4] = {hold.x, hold.y, hold.z, hold.w};
            float hnew[4];
            #pragma unroll
            for (int bb = 0; bb < NBg; bb++) {
                float rr = gate_s[bb][g];
                float zz = gate_s[bb][128 + g];
                float n = tanhf_fast(fmaf(rr, hn_s[bb][g], xn_s[bb][g]));
                float hv = fmaf(zz, ho[bb] - n, n);          // (1-z)*n + z*h
                hnew[bb] = (i < du[bb]) ? hv : ho[bb];       // freeze after segment
            }
            *(float4*)&h4[g][0] = make_float4(hnew[0], hnew[1], hnew[2], hnew[3]);
        }
        __syncthreads();
    }

    if (g < 128) {
        #pragma unroll
        for (int bb = 0; bb < NBg; bb++) {
            int b = b0 + bb;
            float v = (s < src_len[b]) ? h4[g][bb] : 0.f;
            out[(b * Sv + s) * 256 + dir * 128 + g] = v;
        }
    }
}

// ---------------------------------------------------------------------------
extern "C" void kernel_launch(void* const* d_in, const int* in_sizes, int n_in,
                              void* d_out, int out_size) {
    const float* mel      = (const float*)d_in[0];
    const int*   durations= (const int*)d_in[1];
    const int*   mel_len  = (const int*)d_in[2];
    const int*   src_len  = (const int*)d_in[3];
    const float* w1       = (const float*)d_in[4];
    const float* g1       = (const float*)d_in[5];
    const float* be1      = (const float*)d_in[6];
    const float* w2       = (const float*)d_in[7];
    const float* g2       = (const float*)d_in[8];
    const float* be2      = (const float*)d_in[9];
    const float* w_ih_f   = (const float*)d_in[10];
    const float* w_hh_f   = (const float*)d_in[11];
    const float* b_ih_f   = (const float*)d_in[12];
    const float* b_hh_f   = (const float*)d_in[13];
    const float* w_ih_b   = (const float*)d_in[14];
    const float* w_hh_b   = (const float*)d_in[15];
    const float* b_ih_b   = (const float*)d_in[16];
    const float* b_hh_b   = (const float*)d_in[17];
    float* out = (float*)d_out;

    size_t conv_smem = (size_t)(80 * 132) * sizeof(float) + 48 * sizeof(u64);
    size_t proj_smem = (size_t)(80 * 66 + 80 * 129) * sizeof(float);
    cudaFuncSetAttribute(conv_kernel, cudaFuncAttributeMaxDynamicSharedMemorySize, (int)conv_smem);
    cudaFuncSetAttribute(proj_kernel, cudaFuncAttributeMaxDynamicSharedMemorySize, (int)proj_smem);

    conv_kernel<<<Bv * Tv, 128, conv_smem>>>(mel, mel_len, w1, g1, be1, w2, g2, be2);
    proj_kernel<<<dim3(150, 6), 256, proj_smem>>>(w_ih_f, b_ih_f, w_ih_b, b_ih_b);
    gru_kernel<<<400, 384>>>(durations, src_len, w_hh_f, b_hh_f, w_hh_b, b_hh_b, out);
}